// round 3
// baseline (speedup 1.0000x reference)
#include <cuda_runtime.h>
#include <cuda_bf16.h>

#define N0 8192
#define N1 4096
#define N2 2048
#define STEPS 100
#define INF1 0.28f
#define INF2 0.20f

// W0ᵀ partial chunks: 8192 rows / 256 = 32; W1ᵀ: 4096 / 256 = 16
#define CH0 32
#define CH1 16

// ---------------- scratch (device globals; no allocation in kernel_launch) ----
__device__ __nv_bfloat16 g_W0b[(size_t)N0 * N1];   // 64 MB
__device__ __nv_bfloat16 g_W1b[(size_t)N1 * N2];   // 16 MB
__device__ float g_e0[N0];
__device__ float g_e1[N1];
__device__ float g_ract1[N1], g_rout1[N1];
__device__ float g_ract2[N2], g_rout2[N2];
__device__ float g_pbu1[CH0 * N1];                 // 512 KB
__device__ float g_pbu2[CH1 * N2];                 // 128 KB

__device__ __forceinline__ float sigm3(float x) {
    // sigmoid(x - 3)
    return 1.0f / (1.0f + expf(3.0f - x));
}

// unpack 8 bf16 from a uint4 and dot with 8 floats
__device__ __forceinline__ float dot8(uint4 u, float4 rA, float4 rB) {
    __nv_bfloat162 b0 = *reinterpret_cast<__nv_bfloat162*>(&u.x);
    __nv_bfloat162 b1 = *reinterpret_cast<__nv_bfloat162*>(&u.y);
    __nv_bfloat162 b2 = *reinterpret_cast<__nv_bfloat162*>(&u.z);
    __nv_bfloat162 b3 = *reinterpret_cast<__nv_bfloat162*>(&u.w);
    float2 f0 = __bfloat1622float2(b0);
    float2 f1 = __bfloat1622float2(b1);
    float2 f2 = __bfloat1622float2(b2);
    float2 f3 = __bfloat1622float2(b3);
    float s = f0.x * rA.x;
    s = fmaf(f0.y, rA.y, s);
    s = fmaf(f1.x, rA.z, s);
    s = fmaf(f1.y, rA.w, s);
    s = fmaf(f2.x, rB.x, s);
    s = fmaf(f2.y, rB.y, s);
    s = fmaf(f3.x, rB.z, s);
    s = fmaf(f3.y, rB.w, s);
    return s;
}

// ---------------- one-time per-launch setup ----------------------------------
__global__ void k_convert(const float* __restrict__ W0, const float* __restrict__ W1) {
    size_t i = (size_t)blockIdx.x * blockDim.x + threadIdx.x;
    const size_t n0q = (size_t)N0 * N1 / 4;
    const size_t n1q = (size_t)N1 * N2 / 4;
    if (i < n0q) {
        float4 v = __ldg((const float4*)W0 + i);
        __nv_bfloat162 lo = __floats2bfloat162_rn(v.x, v.y);
        __nv_bfloat162 hi = __floats2bfloat162_rn(v.z, v.w);
        uint2 o;
        o.x = *reinterpret_cast<unsigned int*>(&lo);
        o.y = *reinterpret_cast<unsigned int*>(&hi);
        reinterpret_cast<uint2*>(g_W0b)[i] = o;
    } else if (i < n0q + n1q) {
        size_t j = i - n0q;
        float4 v = __ldg((const float4*)W1 + j);
        __nv_bfloat162 lo = __floats2bfloat162_rn(v.x, v.y);
        __nv_bfloat162 hi = __floats2bfloat162_rn(v.z, v.w);
        uint2 o;
        o.x = *reinterpret_cast<unsigned int*>(&lo);
        o.y = *reinterpret_cast<unsigned int*>(&hi);
        reinterpret_cast<uint2*>(g_W1b)[j] = o;
    }
}

__global__ void k_init() {
    int j = blockIdx.x * blockDim.x + threadIdx.x;
    float r0 = sigm3(-2.0f);
    if (j < N1) {
        g_ract1[j] = -2.0f;
        g_rout1[j] = r0;
    } else if (j < N1 + N2) {
        int k = j - N1;
        g_ract2[k] = -2.0f;
        g_rout2[k] = r0;
    }
}

// ---------------- per-step K1: forward matvecs --------------------------------
// e0 = frame - W0 @ r1 ;  e1 = r1 - W1 @ r2
// grid 384 blocks x 256 threads. Blocks [0,256): W0 (2048 warps, 4 rows/warp).
// Blocks [256,384): W1 (1024 warps, 4 rows/warp).
__global__ void k_forward(const float* __restrict__ frame) {
    int tid = threadIdx.x, lane = tid & 31, warp = tid >> 5;
    if (blockIdx.x < 256) {
        int gw = blockIdx.x * 8 + warp;      // 0..2047
        int row0 = gw * 4;
        const uint4* w0 = (const uint4*)(g_W0b + (size_t)row0 * N1);
        const uint4* w1 = (const uint4*)(g_W0b + (size_t)(row0 + 1) * N1);
        const uint4* w2 = (const uint4*)(g_W0b + (size_t)(row0 + 2) * N1);
        const uint4* w3 = (const uint4*)(g_W0b + (size_t)(row0 + 3) * N1);
        const float4* rp = (const float4*)g_rout1;
        float a0 = 0.f, a1 = 0.f, a2 = 0.f, a3 = 0.f;
        #pragma unroll 4
        for (int c = lane; c < N1 / 8; c += 32) {
            float4 rA = __ldg(rp + 2 * c);
            float4 rB = __ldg(rp + 2 * c + 1);
            a0 += dot8(__ldg(w0 + c), rA, rB);
            a1 += dot8(__ldg(w1 + c), rA, rB);
            a2 += dot8(__ldg(w2 + c), rA, rB);
            a3 += dot8(__ldg(w3 + c), rA, rB);
        }
        #pragma unroll
        for (int o = 16; o; o >>= 1) {
            a0 += __shfl_xor_sync(0xFFFFFFFFu, a0, o);
            a1 += __shfl_xor_sync(0xFFFFFFFFu, a1, o);
            a2 += __shfl_xor_sync(0xFFFFFFFFu, a2, o);
            a3 += __shfl_xor_sync(0xFFFFFFFFu, a3, o);
        }
        if (lane == 0) {
            g_e0[row0 + 0] = frame[row0 + 0] - a0;
            g_e0[row0 + 1] = frame[row0 + 1] - a1;
            g_e0[row0 + 2] = frame[row0 + 2] - a2;
            g_e0[row0 + 3] = frame[row0 + 3] - a3;
        }
    } else {
        int gw = (blockIdx.x - 256) * 8 + warp;  // 0..1023
        int row0 = gw * 4;
        const uint4* w0 = (const uint4*)(g_W1b + (size_t)row0 * N2);
        const uint4* w1 = (const uint4*)(g_W1b + (size_t)(row0 + 1) * N2);
        const uint4* w2 = (const uint4*)(g_W1b + (size_t)(row0 + 2) * N2);
        const uint4* w3 = (const uint4*)(g_W1b + (size_t)(row0 + 3) * N2);
        const float4* rp = (const float4*)g_rout2;
        float a0 = 0.f, a1 = 0.f, a2 = 0.f, a3 = 0.f;
        #pragma unroll 4
        for (int c = lane; c < N2 / 8; c += 32) {
            float4 rA = __ldg(rp + 2 * c);
            float4 rB = __ldg(rp + 2 * c + 1);
            a0 += dot8(__ldg(w0 + c), rA, rB);
            a1 += dot8(__ldg(w1 + c), rA, rB);
            a2 += dot8(__ldg(w2 + c), rA, rB);
            a3 += dot8(__ldg(w3 + c), rA, rB);
        }
        #pragma unroll
        for (int o = 16; o; o >>= 1) {
            a0 += __shfl_xor_sync(0xFFFFFFFFu, a0, o);
            a1 += __shfl_xor_sync(0xFFFFFFFFu, a1, o);
            a2 += __shfl_xor_sync(0xFFFFFFFFu, a2, o);
            a3 += __shfl_xor_sync(0xFFFFFFFFu, a3, o);
        }
        if (lane == 0) {
            g_e1[row0 + 0] = g_rout1[row0 + 0] - a0;
            g_e1[row0 + 1] = g_rout1[row0 + 1] - a1;
            g_e1[row0 + 2] = g_rout1[row0 + 2] - a2;
            g_e1[row0 + 3] = g_rout1[row0 + 3] - a3;
        }
    }
}

// ---------------- per-step K2: transpose matvec partials -----------------------
// partial bu1 = W0^T e0 over 256-row chunks; partial bu2 = W1^T e1.
// grid 160 blocks x 128 threads. Blocks [0,128): W0 (4 colblocks x 32 chunks).
// Blocks [128,160): W1 (2 colblocks x 16 chunks). Thread = 8 consecutive cols.
__global__ void k_transpose() {
    __shared__ float s_e[256];
    int tid = threadIdx.x;
    int b = blockIdx.x;
    if (b < 128) {
        int colblock = b & 3;
        int chunk = b >> 2;           // 0..31
        int col0 = colblock * 1024 + tid * 8;
        int row0 = chunk * 256;
        s_e[tid]       = g_e0[row0 + tid];
        s_e[tid + 128] = g_e0[row0 + tid + 128];
        __syncthreads();
        float a[8];
        #pragma unroll
        for (int k = 0; k < 8; k++) a[k] = 0.f;
        const __nv_bfloat16* wbase = g_W0b + (size_t)row0 * N1 + col0;
        #pragma unroll 4
        for (int r = 0; r < 256; r++) {
            uint4 u = *reinterpret_cast<const uint4*>(wbase + (size_t)r * N1);
            float ev = s_e[r];
            __nv_bfloat162 b0 = *reinterpret_cast<__nv_bfloat162*>(&u.x);
            __nv_bfloat162 b1 = *reinterpret_cast<__nv_bfloat162*>(&u.y);
            __nv_bfloat162 b2 = *reinterpret_cast<__nv_bfloat162*>(&u.z);
            __nv_bfloat162 b3 = *reinterpret_cast<__nv_bfloat162*>(&u.w);
            float2 f0 = __bfloat1622float2(b0);
            float2 f1 = __bfloat1622float2(b1);
            float2 f2 = __bfloat1622float2(b2);
            float2 f3 = __bfloat1622float2(b3);
            a[0] = fmaf(f0.x, ev, a[0]);
            a[1] = fmaf(f0.y, ev, a[1]);
            a[2] = fmaf(f1.x, ev, a[2]);
            a[3] = fmaf(f1.y, ev, a[3]);
            a[4] = fmaf(f2.x, ev, a[4]);
            a[5] = fmaf(f2.y, ev, a[5]);
            a[6] = fmaf(f3.x, ev, a[6]);
            a[7] = fmaf(f3.y, ev, a[7]);
        }
        float4* outp = reinterpret_cast<float4*>(&g_pbu1[chunk * N1 + col0]);
        outp[0] = make_float4(a[0], a[1], a[2], a[3]);
        outp[1] = make_float4(a[4], a[5], a[6], a[7]);
    } else {
        int b2 = b - 128;             // 0..31
        int colblock = b2 & 1;
        int chunk = b2 >> 1;          // 0..15
        int col0 = colblock * 1024 + tid * 8;
        int row0 = chunk * 256;
        s_e[tid]       = g_e1[row0 + tid];
        s_e[tid + 128] = g_e1[row0 + tid + 128];
        __syncthreads();
        float a[8];
        #pragma unroll
        for (int k = 0; k < 8; k++) a[k] = 0.f;
        const __nv_bfloat16* wbase = g_W1b + (size_t)row0 * N2 + col0;
        #pragma unroll 4
        for (int r = 0; r < 256; r++) {
            uint4 u = *reinterpret_cast<const uint4*>(wbase + (size_t)r * N2);
            float ev = s_e[r];
            __nv_bfloat162 b0 = *reinterpret_cast<__nv_bfloat162*>(&u.x);
            __nv_bfloat162 b1 = *reinterpret_cast<__nv_bfloat162*>(&u.y);
            __nv_bfloat162 b2 = *reinterpret_cast<__nv_bfloat162*>(&u.z);
            __nv_bfloat162 b3 = *reinterpret_cast<__nv_bfloat162*>(&u.w);
            float2 f0 = __bfloat1622float2(b0);
            float2 f1 = __bfloat1622float2(b1);
            float2 f2 = __bfloat1622float2(b2);
            float2 f3 = __bfloat1622float2(b3);
            a[0] = fmaf(f0.x, ev, a[0]);
            a[1] = fmaf(f0.y, ev, a[1]);
            a[2] = fmaf(f1.x, ev, a[2]);
            a[3] = fmaf(f1.y, ev, a[3]);
            a[4] = fmaf(f2.x, ev, a[4]);
            a[5] = fmaf(f2.y, ev, a[5]);
            a[6] = fmaf(f3.x, ev, a[6]);
            a[7] = fmaf(f3.y, ev, a[7]);
        }
        float4* outp = reinterpret_cast<float4*>(&g_pbu2[chunk * N2 + col0]);
        outp[0] = make_float4(a[0], a[1], a[2], a[3]);
        outp[1] = make_float4(a[4], a[5], a[6], a[7]);
    }
}

// ---------------- per-step K3: deterministic reduce + state update -------------
__global__ void k_update() {
    int j = blockIdx.x * blockDim.x + threadIdx.x;
    if (j < N1) {
        float bu1 = 0.f;
        #pragma unroll
        for (int c = 0; c < CH0; c++) bu1 += g_pbu1[c * N1 + j];
        float e1 = g_e1[j];
        float na = g_ract1[j] + INF1 * (bu1 - e1);
        g_ract1[j] = na;
        g_rout1[j] = sigm3(na);
    } else if (j < N1 + N2) {
        int k = j - N1;
        float bu2 = 0.f;
        #pragma unroll
        for (int c = 0; c < CH1; c++) bu2 += g_pbu2[c * N2 + k];
        float na = g_ract2[k] + INF2 * bu2;
        g_ract2[k] = na;
        g_rout2[k] = sigm3(na);
    }
}

// ---------------- output assembly ---------------------------------------------
__global__ void k_output(float* __restrict__ out) {
    int i = blockIdx.x * blockDim.x + threadIdx.x;
    if (i < N0) {
        out[i] = g_e0[i];
    } else if (i < N0 + N1) {
        out[i] = g_e1[i - N0];
    } else if (i < N0 + 2 * N1) {
        out[i] = g_rout1[i - N0 - N1];
    } else if (i < N0 + 2 * N1 + N2) {
        out[i] = g_rout2[i - N0 - 2 * N1];
    }
}

extern "C" void kernel_launch(void* const* d_in, const int* in_sizes, int n_in,
                              void* d_out, int out_size) {
    const float* frame = (const float*)d_in[0];
    const float* W0    = (const float*)d_in[1];
    const float* W1    = (const float*)d_in[2];
    float* out = (float*)d_out;

    const size_t totq = ((size_t)N0 * N1 + (size_t)N1 * N2) / 4;
    int cvt_blocks = (int)((totq + 255) / 256);
    k_convert<<<cvt_blocks, 256>>>(W0, W1);
    k_init<<<24, 256>>>();

    for (int t = 0; t < STEPS; t++) {
        k_forward<<<384, 256>>>(frame);
        k_transpose<<<160, 128>>>();
        k_update<<<24, 256>>>();
    }
    k_output<<<72, 256>>>(out);
}

// round 5
// speedup vs baseline: 2.6401x; 2.6401x over previous
#include <cuda_runtime.h>
#include <cuda_bf16.h>

#define N0 8192
#define N1 4096
#define N2 2048
#define STEPS 100
#define INF1 0.28f
#define INF2 0.20f

// transpose partial chunks: 32 rows each
#define CH0 256   // 8192 / 32
#define CH1 128   // 4096 / 32

// ---------------- scratch (device globals; no allocation in kernel_launch) ----
__device__ __nv_bfloat16 g_W0b[(size_t)N0 * N1];   // 64 MB
__device__ __nv_bfloat16 g_W1b[(size_t)N1 * N2];   // 16 MB
__device__ float g_e0[N0];
__device__ float g_e1[N1];
__device__ float g_ract1[N1], g_rout1[N1];
__device__ float g_ract2[N2], g_rout2[N2];
__device__ float g_pbu1[CH0 * N1];                 // 4 MB
__device__ float g_pbu2[CH1 * N2];                 // 1 MB

__device__ __forceinline__ float sigm3(float x) {
    // sigmoid(x - 3)
    return 1.0f / (1.0f + expf(3.0f - x));
}

// unpack 8 bf16 from a uint4 and dot with 8 floats
__device__ __forceinline__ float dot8(uint4 u, float4 rA, float4 rB) {
    __nv_bfloat162 b0 = *reinterpret_cast<__nv_bfloat162*>(&u.x);
    __nv_bfloat162 b1 = *reinterpret_cast<__nv_bfloat162*>(&u.y);
    __nv_bfloat162 b2 = *reinterpret_cast<__nv_bfloat162*>(&u.z);
    __nv_bfloat162 b3 = *reinterpret_cast<__nv_bfloat162*>(&u.w);
    float2 f0 = __bfloat1622float2(b0);
    float2 f1 = __bfloat1622float2(b1);
    float2 f2 = __bfloat1622float2(b2);
    float2 f3 = __bfloat1622float2(b3);
    float s = f0.x * rA.x;
    s = fmaf(f0.y, rA.y, s);
    s = fmaf(f1.x, rA.z, s);
    s = fmaf(f1.y, rA.w, s);
    s = fmaf(f2.x, rB.x, s);
    s = fmaf(f2.y, rB.y, s);
    s = fmaf(f3.x, rB.z, s);
    s = fmaf(f3.y, rB.w, s);
    return s;
}

// accumulate 8 columns: a[k] += w[k] * ev
__device__ __forceinline__ void fma8(float* a, uint4 u, float ev) {
    __nv_bfloat162 b0 = *reinterpret_cast<__nv_bfloat162*>(&u.x);
    __nv_bfloat162 b1 = *reinterpret_cast<__nv_bfloat162*>(&u.y);
    __nv_bfloat162 b2 = *reinterpret_cast<__nv_bfloat162*>(&u.z);
    __nv_bfloat162 b3 = *reinterpret_cast<__nv_bfloat162*>(&u.w);
    float2 f0 = __bfloat1622float2(b0);
    float2 f1 = __bfloat1622float2(b1);
    float2 f2 = __bfloat1622float2(b2);
    float2 f3 = __bfloat1622float2(b3);
    a[0] = fmaf(f0.x, ev, a[0]);
    a[1] = fmaf(f0.y, ev, a[1]);
    a[2] = fmaf(f1.x, ev, a[2]);
    a[3] = fmaf(f1.y, ev, a[3]);
    a[4] = fmaf(f2.x, ev, a[4]);
    a[5] = fmaf(f2.y, ev, a[5]);
    a[6] = fmaf(f3.x, ev, a[6]);
    a[7] = fmaf(f3.y, ev, a[7]);
}

// ---------------- one-time per-launch setup ----------------------------------
__global__ void k_convert(const float* __restrict__ W0, const float* __restrict__ W1) {
    size_t i = (size_t)blockIdx.x * blockDim.x + threadIdx.x;
    const size_t n0q = (size_t)N0 * N1 / 4;
    const size_t n1q = (size_t)N1 * N2 / 4;
    if (i < n0q) {
        float4 v = __ldg((const float4*)W0 + i);
        __nv_bfloat162 lo = __floats2bfloat162_rn(v.x, v.y);
        __nv_bfloat162 hi = __floats2bfloat162_rn(v.z, v.w);
        uint2 o;
        o.x = *reinterpret_cast<unsigned int*>(&lo);
        o.y = *reinterpret_cast<unsigned int*>(&hi);
        reinterpret_cast<uint2*>(g_W0b)[i] = o;
    } else if (i < n0q + n1q) {
        size_t j = i - n0q;
        float4 v = __ldg((const float4*)W1 + j);
        __nv_bfloat162 lo = __floats2bfloat162_rn(v.x, v.y);
        __nv_bfloat162 hi = __floats2bfloat162_rn(v.z, v.w);
        uint2 o;
        o.x = *reinterpret_cast<unsigned int*>(&lo);
        o.y = *reinterpret_cast<unsigned int*>(&hi);
        reinterpret_cast<uint2*>(g_W1b)[j] = o;
    }
}

__global__ void k_init() {
    int j = blockIdx.x * blockDim.x + threadIdx.x;
    float r0 = sigm3(-2.0f);
    if (j < N1) {
        g_ract1[j] = -2.0f;
        g_rout1[j] = r0;
    } else if (j < N1 + N2) {
        int k = j - N1;
        g_ract2[k] = -2.0f;
        g_rout2[k] = r0;
    }
}

// ---------------- per-step K1: forward matvecs --------------------------------
// e0 = frame - W0 @ r1 ;  e1 = r1 - W1 @ r2
// 2 rows per warp. Blocks [0,512): W0 (4096 warps -> 8192 rows).
// Blocks [512,768): W1 (2048 warps -> 4096 rows).
__global__ void __launch_bounds__(256) k_forward(const float* __restrict__ frame) {
    int tid = threadIdx.x, lane = tid & 31, warp = tid >> 5;
    int b = blockIdx.x;
    if (b < 512) {
        int gw = b * 8 + warp;               // 0..4095
        int row0 = gw * 2;
        const uint4* w0 = (const uint4*)(g_W0b + (size_t)row0 * N1);
        const uint4* w1 = (const uint4*)(g_W0b + (size_t)(row0 + 1) * N1);
        const float4* rp = (const float4*)g_rout1;
        float a0 = 0.f, a1 = 0.f;
        // 512 uint4 per row, 16 iters per lane
        #pragma unroll 8
        for (int i = 0; i < 16; i++) {
            int c = lane + i * 32;
            float4 rA = __ldg(rp + 2 * c);
            float4 rB = __ldg(rp + 2 * c + 1);
            a0 += dot8(__ldg(w0 + c), rA, rB);
            a1 += dot8(__ldg(w1 + c), rA, rB);
        }
        #pragma unroll
        for (int o = 16; o; o >>= 1) {
            a0 += __shfl_xor_sync(0xFFFFFFFFu, a0, o);
            a1 += __shfl_xor_sync(0xFFFFFFFFu, a1, o);
        }
        if (lane == 0) {
            g_e0[row0 + 0] = frame[row0 + 0] - a0;
            g_e0[row0 + 1] = frame[row0 + 1] - a1;
        }
    } else {
        int gw = (b - 512) * 8 + warp;       // 0..2047
        int row0 = gw * 2;                   // 0..4094 (covers all N1 rows)
        const uint4* w0 = (const uint4*)(g_W1b + (size_t)row0 * N2);
        const uint4* w1 = (const uint4*)(g_W1b + (size_t)(row0 + 1) * N2);
        const float4* rp = (const float4*)g_rout2;
        float a0 = 0.f, a1 = 0.f;
        // 256 uint4 per row, 8 iters per lane
        #pragma unroll
        for (int i = 0; i < 8; i++) {
            int c = lane + i * 32;
            float4 rA = __ldg(rp + 2 * c);
            float4 rB = __ldg(rp + 2 * c + 1);
            a0 += dot8(__ldg(w0 + c), rA, rB);
            a1 += dot8(__ldg(w1 + c), rA, rB);
        }
        #pragma unroll
        for (int o = 16; o; o >>= 1) {
            a0 += __shfl_xor_sync(0xFFFFFFFFu, a0, o);
            a1 += __shfl_xor_sync(0xFFFFFFFFu, a1, o);
        }
        if (lane == 0) {
            g_e1[row0 + 0] = g_rout1[row0 + 0] - a0;
            g_e1[row0 + 1] = g_rout1[row0 + 1] - a1;
        }
    }
}

// ---------------- per-step K2: transpose matvec partials -----------------------
// 32-row chunks. Blocks [0,1024): W0 (4 colblocks x 256 chunks).
// Blocks [1024,1280): W1 (2 colblocks x 128 chunks). Thread = 8 consecutive cols.
__global__ void __launch_bounds__(128) k_transpose() {
    __shared__ float s_e[32];
    int tid = threadIdx.x;
    int b = blockIdx.x;
    if (b < 1024) {
        int colblock = b & 3;
        int chunk = b >> 2;                  // 0..255
        int col0 = colblock * 1024 + tid * 8;
        int row0 = chunk * 32;
        if (tid < 32) s_e[tid] = g_e0[row0 + tid];
        __syncthreads();
        float a[8];
        #pragma unroll
        for (int k = 0; k < 8; k++) a[k] = 0.f;
        const __nv_bfloat16* wbase = g_W0b + (size_t)row0 * N1 + col0;
        #pragma unroll 16
        for (int r = 0; r < 32; r++) {
            uint4 u = *reinterpret_cast<const uint4*>(wbase + (size_t)r * N1);
            fma8(a, u, s_e[r]);
        }
        float4* outp = reinterpret_cast<float4*>(&g_pbu1[chunk * N1 + col0]);
        outp[0] = make_float4(a[0], a[1], a[2], a[3]);
        outp[1] = make_float4(a[4], a[5], a[6], a[7]);
    } else {
        int b2 = b - 1024;                   // 0..255
        int colblock = b2 & 1;
        int chunk = b2 >> 1;                 // 0..127
        int col0 = colblock * 1024 + tid * 8;
        int row0 = chunk * 32;
        if (tid < 32) s_e[tid] = g_e1[row0 + tid];
        __syncthreads();
        float a[8];
        #pragma unroll
        for (int k = 0; k < 8; k++) a[k] = 0.f;
        const __nv_bfloat16* wbase = g_W1b + (size_t)row0 * N2 + col0;
        #pragma unroll 16
        for (int r = 0; r < 32; r++) {
            uint4 u = *reinterpret_cast<const uint4*>(wbase + (size_t)r * N2);
            fma8(a, u, s_e[r]);
        }
        float4* outp = reinterpret_cast<float4*>(&g_pbu2[chunk * N2 + col0]);
        outp[0] = make_float4(a[0], a[1], a[2], a[3]);
        outp[1] = make_float4(a[4], a[5], a[6], a[7]);
    }
}

// ---------------- per-step K3: deterministic reduce + state update -------------
// Blocks [0,16): layer1 columns (coalesced: consecutive threads = consecutive cols).
// Blocks [16,24): layer2 columns.
__global__ void __launch_bounds__(256) k_update() {
    int b = blockIdx.x, tid = threadIdx.x;
    if (b < 16) {
        int col = b * 256 + tid;
        float s0 = 0.f, s1 = 0.f, s2 = 0.f, s3 = 0.f;
        #pragma unroll 8
        for (int c = 0; c < CH0; c += 4) {
            s0 += g_pbu1[(c + 0) * N1 + col];
            s1 += g_pbu1[(c + 1) * N1 + col];
            s2 += g_pbu1[(c + 2) * N1 + col];
            s3 += g_pbu1[(c + 3) * N1 + col];
        }
        float bu1 = (s0 + s1) + (s2 + s3);
        float na = g_ract1[col] + INF1 * (bu1 - g_e1[col]);
        g_ract1[col] = na;
        g_rout1[col] = sigm3(na);
    } else {
        int col = (b - 16) * 256 + tid;
        float s0 = 0.f, s1 = 0.f, s2 = 0.f, s3 = 0.f;
        #pragma unroll 8
        for (int c = 0; c < CH1; c += 4) {
            s0 += g_pbu2[(c + 0) * N2 + col];
            s1 += g_pbu2[(c + 1) * N2 + col];
            s2 += g_pbu2[(c + 2) * N2 + col];
            s3 += g_pbu2[(c + 3) * N2 + col];
        }
        float bu2 = (s0 + s1) + (s2 + s3);
        float na = g_ract2[col] + INF2 * bu2;
        g_ract2[col] = na;
        g_rout2[col] = sigm3(na);
    }
}

// ---------------- output assembly ---------------------------------------------
__global__ void k_output(float* __restrict__ out) {
    int i = blockIdx.x * blockDim.x + threadIdx.x;
    if (i < N0) {
        out[i] = g_e0[i];
    } else if (i < N0 + N1) {
        out[i] = g_e1[i - N0];
    } else if (i < N0 + 2 * N1) {
        out[i] = g_rout1[i - N0 - N1];
    } else if (i < N0 + 2 * N1 + N2) {
        out[i] = g_rout2[i - N0 - 2 * N1];
    }
}

extern "C" void kernel_launch(void* const* d_in, const int* in_sizes, int n_in,
                              void* d_out, int out_size) {
    const float* frame = (const float*)d_in[0];
    const float* W0    = (const float*)d_in[1];
    const float* W1    = (const float*)d_in[2];
    float* out = (float*)d_out;

    const size_t totq = ((size_t)N0 * N1 + (size_t)N1 * N2) / 4;
    int cvt_blocks = (int)((totq + 255) / 256);
    k_convert<<<cvt_blocks, 256>>>(W0, W1);
    k_init<<<24, 256>>>();

    for (int t = 0; t < STEPS; t++) {
        k_forward<<<768, 256>>>(frame);
        k_transpose<<<1280, 128>>>();
        k_update<<<24, 256>>>();
    }
    k_output<<<72, 256>>>(out);
}

// round 6
// speedup vs baseline: 3.6490x; 1.3821x over previous
#include <cuda_runtime.h>
#include <cuda_bf16.h>
#include <cuda_fp16.h>

#define N0 8192
#define N1 4096
#define N2 2048
#define STEPS 100
#define INF1 0.28f
#define INF2 0.20f
#define WSCALE 4096.0f
#define INV_WSCALE (1.0f / 4096.0f)

// transpose partial chunks: 32 rows each
#define CH0 256   // 8192 / 32
#define CH1 128   // 4096 / 32

// ---------------- scratch (device globals; no allocation in kernel_launch) ----
__device__ unsigned char g_W0f8[(size_t)N0 * N1];   // 32 MB, e4m3 = W0 * 4096
__device__ unsigned char g_W1f8[(size_t)N1 * N2];   // 8 MB,  e4m3 = W1 * 4096
__device__ float g_e0[N0];
__device__ float g_e1[N1];
__device__ float g_ract1[N1], g_rout1[N1];
__device__ float g_ract2[N2], g_rout2[N2];
__device__ __half g_rh1[N1];                        // f16 copy of r_out1
__device__ __half g_rh2[N2];                        // f16 copy of r_out2
__device__ float g_pbu1[CH0 * N1];                  // 4 MB
__device__ float g_pbu2[CH1 * N2];                  // 1 MB

__device__ __forceinline__ float sigm3(float x) {
    // sigmoid(x - 3)
    return 1.0f / (1.0f + expf(3.0f - x));
}

// pack 4 floats -> 4 e4m3 bytes (byte0 = v.x ... byte3 = v.w)
__device__ __forceinline__ unsigned pack4_e4m3(float4 v) {
    unsigned short lo, hi;
    asm("cvt.rn.satfinite.e4m3x2.f32 %0, %1, %2;" : "=h"(lo) : "f"(v.y), "f"(v.x));
    asm("cvt.rn.satfinite.e4m3x2.f32 %0, %1, %2;" : "=h"(hi) : "f"(v.w), "f"(v.z));
    return (unsigned)lo | ((unsigned)hi << 16);
}

// decode u32 (4 e4m3) -> two __half2 (a = vals 0,1 ; b = vals 2,3)
__device__ __forceinline__ void u32_to_2h2(unsigned u, __half2& a, __half2& b) {
    unsigned ra, rb;
    asm("{\n\t"
        ".reg .b16 lo, hi;\n\t"
        "mov.b32 {lo, hi}, %2;\n\t"
        "cvt.rn.f16x2.e4m3x2 %0, lo;\n\t"
        "cvt.rn.f16x2.e4m3x2 %1, hi;\n\t"
        "}"
        : "=r"(ra), "=r"(rb) : "r"(u));
    a = *reinterpret_cast<__half2*>(&ra);
    b = *reinterpret_cast<__half2*>(&rb);
}

__device__ __forceinline__ __half2 as_h2(unsigned u) {
    return *reinterpret_cast<__half2*>(&u);
}

// ---------------- one-time per-launch setup ----------------------------------
__global__ void k_convert(const float* __restrict__ W0, const float* __restrict__ W1) {
    size_t i = (size_t)blockIdx.x * blockDim.x + threadIdx.x;
    const size_t n0q = (size_t)N0 * N1 / 4;
    const size_t n1q = (size_t)N1 * N2 / 4;
    if (i < n0q) {
        float4 v = __ldg((const float4*)W0 + i);
        v.x *= WSCALE; v.y *= WSCALE; v.z *= WSCALE; v.w *= WSCALE;
        reinterpret_cast<unsigned*>(g_W0f8)[i] = pack4_e4m3(v);
    } else if (i < n0q + n1q) {
        size_t j = i - n0q;
        float4 v = __ldg((const float4*)W1 + j);
        v.x *= WSCALE; v.y *= WSCALE; v.z *= WSCALE; v.w *= WSCALE;
        reinterpret_cast<unsigned*>(g_W1f8)[j] = pack4_e4m3(v);
    }
}

__global__ void k_init() {
    int j = blockIdx.x * blockDim.x + threadIdx.x;
    float r0 = sigm3(-2.0f);
    if (j < N1) {
        g_ract1[j] = -2.0f;
        g_rout1[j] = r0;
        g_rh1[j] = __float2half(r0);
    } else if (j < N1 + N2) {
        int k = j - N1;
        g_ract2[k] = -2.0f;
        g_rout2[k] = r0;
        g_rh2[k] = __float2half(r0);
    }
}

// dot of one fp8 uint4 (16 w) against 16 r halves (2 uint4 of __half2), f16 chain
__device__ __forceinline__ void dot16_f8(uint4 wq, uint4 rq0, uint4 rq1, float& acc) {
    __half2 h = __float2half2_rn(0.0f);
    __half2 a, b;
    u32_to_2h2(wq.x, a, b);
    h = __hfma2(a, as_h2(rq0.x), h);
    h = __hfma2(b, as_h2(rq0.y), h);
    u32_to_2h2(wq.y, a, b);
    h = __hfma2(a, as_h2(rq0.z), h);
    h = __hfma2(b, as_h2(rq0.w), h);
    u32_to_2h2(wq.z, a, b);
    h = __hfma2(a, as_h2(rq1.x), h);
    h = __hfma2(b, as_h2(rq1.y), h);
    u32_to_2h2(wq.w, a, b);
    h = __hfma2(a, as_h2(rq1.z), h);
    h = __hfma2(b, as_h2(rq1.w), h);
    float2 f = __half22float2(h);
    acc += f.x + f.y;
}

// ---------------- per-step K1: forward matvecs --------------------------------
// e0 = frame - W0 @ r1 ;  e1 = r1 - W1 @ r2
// 2 rows per warp. Blocks [0,512): W0 (4096 warps -> 8192 rows).
// Blocks [512,768): W1 (2048 warps -> 4096 rows).
__global__ void __launch_bounds__(256) k_forward(const float* __restrict__ frame) {
    int tid = threadIdx.x, lane = tid & 31, warp = tid >> 5;
    int b = blockIdx.x;
    if (b < 512) {
        int gw = b * 8 + warp;               // 0..4095
        int row0 = gw * 2;
        const uint4* w0 = (const uint4*)(g_W0f8 + (size_t)row0 * N1);
        const uint4* w1 = (const uint4*)(g_W0f8 + (size_t)(row0 + 1) * N1);
        const uint4* rp = (const uint4*)g_rh1;   // 512 uint4 = 4096 halves
        float a0 = 0.f, a1 = 0.f;
        // 256 uint4 per row (16 fp8 each), 8 iters per lane
        #pragma unroll
        for (int i = 0; i < 8; i++) {
            int c = lane + i * 32;
            uint4 rq0 = __ldg(rp + 2 * c);
            uint4 rq1 = __ldg(rp + 2 * c + 1);
            dot16_f8(__ldg(w0 + c), rq0, rq1, a0);
            dot16_f8(__ldg(w1 + c), rq0, rq1, a1);
        }
        #pragma unroll
        for (int o = 16; o; o >>= 1) {
            a0 += __shfl_xor_sync(0xFFFFFFFFu, a0, o);
            a1 += __shfl_xor_sync(0xFFFFFFFFu, a1, o);
        }
        if (lane == 0) {
            g_e0[row0 + 0] = frame[row0 + 0] - a0 * INV_WSCALE;
            g_e0[row0 + 1] = frame[row0 + 1] - a1 * INV_WSCALE;
        }
    } else {
        int gw = (b - 512) * 8 + warp;       // 0..2047
        int row0 = gw * 2;                   // 0..4094
        const uint4* w0 = (const uint4*)(g_W1f8 + (size_t)row0 * N2);
        const uint4* w1 = (const uint4*)(g_W1f8 + (size_t)(row0 + 1) * N2);
        const uint4* rp = (const uint4*)g_rh2;   // 256 uint4 = 2048 halves
        float a0 = 0.f, a1 = 0.f;
        // 128 uint4 per row, 4 iters per lane
        #pragma unroll
        for (int i = 0; i < 4; i++) {
            int c = lane + i * 32;
            uint4 rq0 = __ldg(rp + 2 * c);
            uint4 rq1 = __ldg(rp + 2 * c + 1);
            dot16_f8(__ldg(w0 + c), rq0, rq1, a0);
            dot16_f8(__ldg(w1 + c), rq0, rq1, a1);
        }
        #pragma unroll
        for (int o = 16; o; o >>= 1) {
            a0 += __shfl_xor_sync(0xFFFFFFFFu, a0, o);
            a1 += __shfl_xor_sync(0xFFFFFFFFu, a1, o);
        }
        if (lane == 0) {
            g_e1[row0 + 0] = g_rout1[row0 + 0] - a0 * INV_WSCALE;
            g_e1[row0 + 1] = g_rout1[row0 + 1] - a1 * INV_WSCALE;
        }
    }
}

// ---------------- per-step K2: transpose matvec partials -----------------------
// 32-row chunks, thread = 16 consecutive cols (one fp8 uint4 per row).
// Blocks [0,512): W0 (2 colblocks x 256 chunks).
// Blocks [512,640): W1 (1 colblock x 128 chunks).
__global__ void __launch_bounds__(128) k_transpose() {
    __shared__ __half2 s_eh[32];
    int tid = threadIdx.x;
    int b = blockIdx.x;

    const unsigned char* wmat;
    float* pbu;
    int col0, row0, chunk, ldw;
    if (b < 512) {
        int colblock = b & 1;
        chunk = b >> 1;                      // 0..255
        col0 = colblock * 2048 + tid * 16;
        row0 = chunk * 32;
        if (tid < 32) s_eh[tid] = __float2half2_rn(g_e0[row0 + tid]);
        wmat = g_W0f8;
        pbu = g_pbu1;
        ldw = N1;
    } else {
        int b2 = b - 512;                    // 0..127
        chunk = b2;
        col0 = tid * 16;
        row0 = chunk * 32;
        if (tid < 32) s_eh[tid] = __float2half2_rn(g_e1[row0 + tid]);
        wmat = g_W1f8;
        pbu = g_pbu2;
        ldw = N2;
    }
    __syncthreads();

    const unsigned char* wbase = wmat + (size_t)row0 * ldw + col0;
    float facc[16];
    #pragma unroll
    for (int k = 0; k < 16; k++) facc[k] = 0.f;

    #pragma unroll
    for (int seg = 0; seg < 2; seg++) {
        __half2 acc[8];
        #pragma unroll
        for (int k = 0; k < 8; k++) acc[k] = __float2half2_rn(0.0f);
        #pragma unroll
        for (int r = 0; r < 16; r++) {
            uint4 u = *reinterpret_cast<const uint4*>(wbase + (size_t)(seg * 16 + r) * ldw);
            __half2 ev = s_eh[seg * 16 + r];
            __half2 a, bb;
            u32_to_2h2(u.x, a, bb);
            acc[0] = __hfma2(a, ev, acc[0]);
            acc[1] = __hfma2(bb, ev, acc[1]);
            u32_to_2h2(u.y, a, bb);
            acc[2] = __hfma2(a, ev, acc[2]);
            acc[3] = __hfma2(bb, ev, acc[3]);
            u32_to_2h2(u.z, a, bb);
            acc[4] = __hfma2(a, ev, acc[4]);
            acc[5] = __hfma2(bb, ev, acc[5]);
            u32_to_2h2(u.w, a, bb);
            acc[6] = __hfma2(a, ev, acc[6]);
            acc[7] = __hfma2(bb, ev, acc[7]);
        }
        #pragma unroll
        for (int k = 0; k < 8; k++) {
            float2 f = __half22float2(acc[k]);
            facc[2 * k]     += f.x;
            facc[2 * k + 1] += f.y;
        }
    }

    float4* outp = reinterpret_cast<float4*>(&pbu[chunk * ldw + col0]);
    outp[0] = make_float4(facc[0], facc[1], facc[2], facc[3]);
    outp[1] = make_float4(facc[4], facc[5], facc[6], facc[7]);
    outp[2] = make_float4(facc[8], facc[9], facc[10], facc[11]);
    outp[3] = make_float4(facc[12], facc[13], facc[14], facc[15]);
}

// ---------------- per-step K3: deterministic reduce + state update -------------
// Blocks [0,16): layer1 columns. Blocks [16,24): layer2 columns.
__global__ void __launch_bounds__(256) k_update() {
    int b = blockIdx.x, tid = threadIdx.x;
    if (b < 16) {
        int col = b * 256 + tid;
        float s0 = 0.f, s1 = 0.f, s2 = 0.f, s3 = 0.f;
        #pragma unroll 8
        for (int c = 0; c < CH0; c += 4) {
            s0 += g_pbu1[(c + 0) * N1 + col];
            s1 += g_pbu1[(c + 1) * N1 + col];
            s2 += g_pbu1[(c + 2) * N1 + col];
            s3 += g_pbu1[(c + 3) * N1 + col];
        }
        float bu1 = ((s0 + s1) + (s2 + s3)) * INV_WSCALE;
        float na = g_ract1[col] + INF1 * (bu1 - g_e1[col]);
        g_ract1[col] = na;
        float ro = sigm3(na);
        g_rout1[col] = ro;
        g_rh1[col] = __float2half(ro);
    } else {
        int col = (b - 16) * 256 + tid;
        float s0 = 0.f, s1 = 0.f, s2 = 0.f, s3 = 0.f;
        #pragma unroll 8
        for (int c = 0; c < CH1; c += 4) {
            s0 += g_pbu2[(c + 0) * N2 + col];
            s1 += g_pbu2[(c + 1) * N2 + col];
            s2 += g_pbu2[(c + 2) * N2 + col];
            s3 += g_pbu2[(c + 3) * N2 + col];
        }
        float bu2 = ((s0 + s1) + (s2 + s3)) * INV_WSCALE;
        float na = g_ract2[col] + INF2 * bu2;
        g_ract2[col] = na;
        float ro = sigm3(na);
        g_rout2[col] = ro;
        g_rh2[col] = __float2half(ro);
    }
}

// ---------------- output assembly ---------------------------------------------
__global__ void k_output(float* __restrict__ out) {
    int i = blockIdx.x * blockDim.x + threadIdx.x;
    if (i < N0) {
        out[i] = g_e0[i];
    } else if (i < N0 + N1) {
        out[i] = g_e1[i - N0];
    } else if (i < N0 + 2 * N1) {
        out[i] = g_rout1[i - N0 - N1];
    } else if (i < N0 + 2 * N1 + N2) {
        out[i] = g_rout2[i - N0 - 2 * N1];
    }
}

extern "C" void kernel_launch(void* const* d_in, const int* in_sizes, int n_in,
                              void* d_out, int out_size) {
    const float* frame = (const float*)d_in[0];
    const float* W0    = (const float*)d_in[1];
    const float* W1    = (const float*)d_in[2];
    float* out = (float*)d_out;

    const size_t totq = ((size_t)N0 * N1 + (size_t)N1 * N2) / 4;
    int cvt_blocks = (int)((totq + 255) / 256);
    k_convert<<<cvt_blocks, 256>>>(W0, W1);
    k_init<<<24, 256>>>();

    for (int t = 0; t < STEPS; t++) {
        k_forward<<<768, 256>>>(frame);
        k_transpose<<<640, 128>>>();
        k_update<<<24, 256>>>();
    }
    k_output<<<72, 256>>>(out);
}

// round 8
// speedup vs baseline: 3.9571x; 1.0844x over previous
#include <cuda_runtime.h>
#include <cuda_bf16.h>
#include <cuda_fp16.h>

#define N0 8192
#define N1 4096
#define N2 2048
#define STEPS 100
#define INF1 0.28f
#define INF2 0.20f
#define WSCALE 4096.0f
#define INV_WSCALE (1.0f / 4096.0f)

// transpose partial chunks: 16 rows each
#define CH0 512   // 8192 / 16
#define CH1 256   // 4096 / 16

// ---------------- scratch (device globals; no allocation in kernel_launch) ----
__device__ unsigned char g_W0f8[(size_t)N0 * N1];   // 32 MB, e4m3 = W0 * 4096
__device__ unsigned char g_W1f8[(size_t)N1 * N2];   // 8 MB,  e4m3 = W1 * 4096
__device__ float g_e0[N0];
__device__ float g_e1[N1];
__device__ float g_ract1[N1], g_rout1[N1];
__device__ float g_ract2[N2], g_rout2[N2];
__device__ __half g_rh1[N1];                        // f16 copy of r_out1
__device__ __half g_rh2[N2];                        // f16 copy of r_out2
__device__ float g_pbu1[CH0 * N1];                  // 8 MB
__device__ float g_pbu2[CH1 * N2];                  // 2 MB

__device__ __forceinline__ float sigm3(float x) {
    // sigmoid(x - 3)
    return 1.0f / (1.0f + expf(3.0f - x));
}

// pack 4 floats -> 4 e4m3 bytes (byte0 = v.x ... byte3 = v.w)
__device__ __forceinline__ unsigned pack4_e4m3(float4 v) {
    unsigned short lo, hi;
    asm("cvt.rn.satfinite.e4m3x2.f32 %0, %1, %2;" : "=h"(lo) : "f"(v.y), "f"(v.x));
    asm("cvt.rn.satfinite.e4m3x2.f32 %0, %1, %2;" : "=h"(hi) : "f"(v.w), "f"(v.z));
    return (unsigned)lo | ((unsigned)hi << 16);
}

// decode u32 (4 e4m3) -> two __half2 (a = vals 0,1 ; b = vals 2,3)
__device__ __forceinline__ void u32_to_2h2(unsigned u, __half2& a, __half2& b) {
    unsigned ra, rb;
    asm("{\n\t"
        ".reg .b16 lo, hi;\n\t"
        "mov.b32 {lo, hi}, %2;\n\t"
        "cvt.rn.f16x2.e4m3x2 %0, lo;\n\t"
        "cvt.rn.f16x2.e4m3x2 %1, hi;\n\t"
        "}"
        : "=r"(ra), "=r"(rb) : "r"(u));
    a = *reinterpret_cast<__half2*>(&ra);
    b = *reinterpret_cast<__half2*>(&rb);
}

__device__ __forceinline__ __half2 as_h2(unsigned u) {
    return *reinterpret_cast<__half2*>(&u);
}

// ---------------- one-time per-launch setup ----------------------------------
__global__ void k_convert(const float* __restrict__ W0, const float* __restrict__ W1) {
    size_t i = (size_t)blockIdx.x * blockDim.x + threadIdx.x;
    const size_t n0q = (size_t)N0 * N1 / 4;
    const size_t n1q = (size_t)N1 * N2 / 4;
    if (i < n0q) {
        float4 v = __ldg((const float4*)W0 + i);
        v.x *= WSCALE; v.y *= WSCALE; v.z *= WSCALE; v.w *= WSCALE;
        reinterpret_cast<unsigned*>(g_W0f8)[i] = pack4_e4m3(v);
    } else if (i < n0q + n1q) {
        size_t j = i - n0q;
        float4 v = __ldg((const float4*)W1 + j);
        v.x *= WSCALE; v.y *= WSCALE; v.z *= WSCALE; v.w *= WSCALE;
        reinterpret_cast<unsigned*>(g_W1f8)[j] = pack4_e4m3(v);
    }
}

__global__ void k_init() {
    int j = blockIdx.x * blockDim.x + threadIdx.x;
    float r0 = sigm3(-2.0f);
    if (j < N1) {
        g_ract1[j] = -2.0f;
        g_rout1[j] = r0;
        g_rh1[j] = __float2half(r0);
    } else if (j < N1 + N2) {
        int k = j - N1;
        g_ract2[k] = -2.0f;
        g_rout2[k] = r0;
        g_rh2[k] = __float2half(r0);
    }
}

// dot of one fp8 uint4 (16 w) against 16 r halves (2 uint4 of __half2), f16 chain
__device__ __forceinline__ void dot16_f8(uint4 wq, uint4 rq0, uint4 rq1, float& acc) {
    __half2 h = __float2half2_rn(0.0f);
    __half2 a, b;
    u32_to_2h2(wq.x, a, b);
    h = __hfma2(a, as_h2(rq0.x), h);
    h = __hfma2(b, as_h2(rq0.y), h);
    u32_to_2h2(wq.y, a, b);
    h = __hfma2(a, as_h2(rq0.z), h);
    h = __hfma2(b, as_h2(rq0.w), h);
    u32_to_2h2(wq.z, a, b);
    h = __hfma2(a, as_h2(rq1.x), h);
    h = __hfma2(b, as_h2(rq1.y), h);
    u32_to_2h2(wq.w, a, b);
    h = __hfma2(a, as_h2(rq1.z), h);
    h = __hfma2(b, as_h2(rq1.w), h);
    float2 f = __half22float2(h);
    acc += f.x + f.y;
}

// ---------------- per-step K1: forward matvecs --------------------------------
// e0 = frame - W0 @ r1 ;  e1 = r1 - W1 @ r2
// 1 row per warp. Blocks [0,1024): W0 (8192 warps -> 8192 rows).
// Blocks [1024,1536): W1 (4096 warps -> 4096 rows).
__global__ void __launch_bounds__(256) k_forward(const float* __restrict__ frame) {
    int tid = threadIdx.x, lane = tid & 31, warp = tid >> 5;
    int b = blockIdx.x;
    if (b < 1024) {
        int row = b * 8 + warp;              // 0..8191
        const uint4* w0 = (const uint4*)(g_W0f8 + (size_t)row * N1);
        const uint4* rp = (const uint4*)g_rh1;   // 512 uint4 = 4096 halves
        float a0 = 0.f;
        // 256 uint4 per row (16 fp8 each), 8 iters per lane
        #pragma unroll
        for (int i = 0; i < 8; i++) {
            int c = lane + i * 32;
            uint4 rq0 = __ldg(rp + 2 * c);
            uint4 rq1 = __ldg(rp + 2 * c + 1);
            dot16_f8(__ldg(w0 + c), rq0, rq1, a0);
        }
        #pragma unroll
        for (int o = 16; o; o >>= 1) a0 += __shfl_xor_sync(0xFFFFFFFFu, a0, o);
        if (lane == 0) g_e0[row] = frame[row] - a0 * INV_WSCALE;
    } else {
        int row = (b - 1024) * 8 + warp;     // 0..4095
        const uint4* w0 = (const uint4*)(g_W1f8 + (size_t)row * N2);
        const uint4* rp = (const uint4*)g_rh2;   // 256 uint4 = 2048 halves
        float a0 = 0.f;
        // 128 uint4 per row, 4 iters per lane
        #pragma unroll
        for (int i = 0; i < 4; i++) {
            int c = lane + i * 32;
            uint4 rq0 = __ldg(rp + 2 * c);
            uint4 rq1 = __ldg(rp + 2 * c + 1);
            dot16_f8(__ldg(w0 + c), rq0, rq1, a0);
        }
        #pragma unroll
        for (int o = 16; o; o >>= 1) a0 += __shfl_xor_sync(0xFFFFFFFFu, a0, o);
        if (lane == 0) g_e1[row] = g_rout1[row] - a0 * INV_WSCALE;
    }
}

// ---------------- per-step K2: transpose matvec partials -----------------------
// 16-row chunks, thread = 16 consecutive cols (one fp8 uint4 per row, 16 loads).
// Blocks [0,1024): W0 (2 colblocks x 512 chunks).
// Blocks [1024,1280): W1 (1 colblock x 256 chunks).
__global__ void __launch_bounds__(128) k_transpose() {
    __shared__ __half2 s_eh[16];
    int tid = threadIdx.x;
    int b = blockIdx.x;

    const unsigned char* wmat;
    float* pbu;
    int col0, row0, chunk, ldw;
    if (b < 1024) {
        int colblock = b & 1;
        chunk = b >> 1;                      // 0..511
        col0 = colblock * 2048 + tid * 16;
        row0 = chunk * 16;
        if (tid < 16) s_eh[tid] = __float2half2_rn(g_e0[row0 + tid]);
        wmat = g_W0f8;
        pbu = g_pbu1;
        ldw = N1;
    } else {
        chunk = b - 1024;                    // 0..255
        col0 = tid * 16;
        row0 = chunk * 16;
        if (tid < 16) s_eh[tid] = __float2half2_rn(g_e1[row0 + tid]);
        wmat = g_W1f8;
        pbu = g_pbu2;
        ldw = N2;
    }
    __syncthreads();

    const unsigned char* wbase = wmat + (size_t)row0 * ldw + col0;

    __half2 acc[8];
    #pragma unroll
    for (int k = 0; k < 8; k++) acc[k] = __float2half2_rn(0.0f);
    #pragma unroll
    for (int r = 0; r < 16; r++) {
        uint4 u = *reinterpret_cast<const uint4*>(wbase + (size_t)r * ldw);
        __half2 ev = s_eh[r];
        __half2 a, bb;
        u32_to_2h2(u.x, a, bb);
        acc[0] = __hfma2(a, ev, acc[0]);
        acc[1] = __hfma2(bb, ev, acc[1]);
        u32_to_2h2(u.y, a, bb);
        acc[2] = __hfma2(a, ev, acc[2]);
        acc[3] = __hfma2(bb, ev, acc[3]);
        u32_to_2h2(u.z, a, bb);
        acc[4] = __hfma2(a, ev, acc[4]);
        acc[5] = __hfma2(bb, ev, acc[5]);
        u32_to_2h2(u.w, a, bb);
        acc[6] = __hfma2(a, ev, acc[6]);
        acc[7] = __hfma2(bb, ev, acc[7]);
    }

    float facc[16];
    #pragma unroll
    for (int k = 0; k < 8; k++) {
        float2 f = __half22float2(acc[k]);
        facc[2 * k]     = f.x;
        facc[2 * k + 1] = f.y;
    }

    float4* outp = reinterpret_cast<float4*>(&pbu[chunk * ldw + col0]);
    outp[0] = make_float4(facc[0], facc[1], facc[2], facc[3]);
    outp[1] = make_float4(facc[4], facc[5], facc[6], facc[7]);
    outp[2] = make_float4(facc[8], facc[9], facc[10], facc[11]);
    outp[3] = make_float4(facc[12], facc[13], facc[14], facc[15]);
}

// ---------------- per-step K3: deterministic reduce + state update -------------
// Block = 256 thr as (32 cols x 8 chunk-groups). Blocks [0,128): layer1 (32 cols
// each). Blocks [128,192): layer2.
__global__ void __launch_bounds__(256) k_update() {
    __shared__ float s[256];
    int b = blockIdx.x;
    int cx = threadIdx.x & 31;     // col within group
    int gy = threadIdx.x >> 5;     // chunk group 0..7
    if (b < 128) {
        int col = b * 32 + cx;
        float s0 = 0.f;
        // CH0 = 512 chunks -> 64 per group
        #pragma unroll 16
        for (int i = 0; i < 64; i++)
            s0 += g_pbu1[(gy * 64 + i) * N1 + col];
        s[threadIdx.x] = s0;
        __syncthreads();
        if (gy == 0) {
            float tot = 0.f;
            #pragma unroll
            for (int g = 0; g < 8; g++) tot += s[g * 32 + cx];
            float bu1 = tot * INV_WSCALE;
            float na = g_ract1[col] + INF1 * (bu1 - g_e1[col]);
            g_ract1[col] = na;
            float ro = sigm3(na);
            g_rout1[col] = ro;
            g_rh1[col] = __float2half(ro);
        }
    } else {
        int col = (b - 128) * 32 + cx;
        float s0 = 0.f;
        // CH1 = 256 chunks -> 32 per group
        #pragma unroll 16
        for (int i = 0; i < 32; i++)
            s0 += g_pbu2[(gy * 32 + i) * N2 + col];
        s[threadIdx.x] = s0;
        __syncthreads();
        if (gy == 0) {
            float tot = 0.f;
            #pragma unroll
            for (int g = 0; g < 8; g++) tot += s[g * 32 + cx];
            float bu2 = tot * INV_WSCALE;
            float na = g_ract2[col] + INF2 * bu2;
            g_ract2[col] = na;
            float ro = sigm3(na);
            g_rout2[col] = ro;
            g_rh2[col] = __float2half(ro);
        }
    }
}

// ---------------- output assembly ---------------------------------------------
__global__ void k_output(float* __restrict__ out) {
    int i = blockIdx.x * blockDim.x + threadIdx.x;
    if (i < N0) {
        out[i] = g_e0[i];
    } else if (i < N0 + N1) {
        out[i] = g_e1[i - N0];
    } else if (i < N0 + 2 * N1) {
        out[i] = g_rout1[i - N0 - N1];
    } else if (i < N0 + 2 * N1 + N2) {
        out[i] = g_rout2[i - N0 - 2 * N1];
    }
}

extern "C" void kernel_launch(void* const* d_in, const int* in_sizes, int n_in,
                              void* d_out, int out_size) {
    const float* frame = (const float*)d_in[0];
    const float* W0    = (const float*)d_in[1];
    const float* W1    = (const float*)d_in[2];
    float* out = (float*)d_out;

    const size_t totq = ((size_t)N0 * N1 + (size_t)N1 * N2) / 4;
    int cvt_blocks = (int)((totq + 255) / 256);
    k_convert<<<cvt_blocks, 256>>>(W0, W1);
    k_init<<<24, 256>>>();

    for (int t = 0; t < STEPS; t++) {
        k_forward<<<1536, 256>>>(frame);
        k_transpose<<<1280, 128>>>();
        k_update<<<192, 256>>>();
    }
    k_output<<<72, 256>>>(out);
}